// round 1
// baseline (speedup 1.0000x reference)
#include <cuda_runtime.h>
#include <math.h>

// Problem constants (fixed by the dataset): B=32, C_in=C_out=128, H=W=64.
#define HW    4096          // 64*64
#define NPIX  131072        // 32*4096 pixels
#define NCH   128

// ---------------- scratch (device globals; no runtime allocation) ----------
__device__ float g_fmax[(size_t)NCH * NPIX];      // 64 MiB, x-layout [(b*128+c)*4096+hw]
__device__ float g_Y[(size_t)256 * NPIX];         // 128 MiB, [ch][pixel_global]
__device__ float g_H[(size_t)128 * NPIX];         // 64 MiB,  [ch][pixel_global]
__device__ float g_Wfold[128 * 256];
__device__ float g_ypart[256 * 1024 * 2];         // per (ch, pixel-tile): {sum, sumsq}
__device__ float g_hpart[128 * 1024 * 2];
__device__ float g_a[256];                        // g/sigma per Y channel (0..127: w_in/BN2, 128..255: w_diff/BN1)
__device__ float g_b2n[128];                      // beta2 - a2*mu2  (x_proc affine shift)
__device__ float g_a3[128];                       // g_mbn/sigma_h
__device__ float g_d3[128];                       // be_mbn - a3*mu_h

__device__ __forceinline__ float gelu_exact(float v) {
    return 0.5f * v * (1.0f + erff(v * 0.70710678118654752f));
}

// ---------------- K1: fmax = x - min over {self, row±s, col±s}, s in {2,4,8,16,32}
__global__ void k_fmax(const float* __restrict__ x) {
    __shared__ float sm[4096];
    int plane = blockIdx.x;                        // b*128 + c
    const float* xp = x + (size_t)plane * HW;
    float* fp = g_fmax + (size_t)plane * HW;
    for (int i = threadIdx.x; i < 4096; i += 256) sm[i] = xp[i];
    __syncthreads();
    for (int i = threadIdx.x; i < 4096; i += 256) {
        int h = i >> 6, w = i & 63;
        float v = sm[i];
        float m = v;
        #pragma unroll
        for (int s = 2; s <= 32; s <<= 1) {
            m = fminf(m, sm[(h << 6) | ((w + s) & 63)]);
            m = fminf(m, sm[(h << 6) | ((w - s) & 63)]);
            m = fminf(m, sm[((((h + s) & 63)) << 6) | w]);
            m = fminf(m, sm[((((h - s) & 63)) << 6) | w]);
        }
        fp[i] = v - m;
    }
}

// ---------------- K2: Y[o][p] = sum_k W[o][k] * X[k][p]  (K=128), + stat partials
// grid (1024 pixel-tiles, 2 out-tiles). out-tile 0: w_in applied to x; 1: w_diff to fmax.
__global__ __launch_bounds__(256, 2) void k_convY(
    const float* __restrict__ x, const float* __restrict__ w_in,
    const float* __restrict__ w_diff) {
    __shared__ float Ws[32][129];   // [k][o], padded: conflict-free transpose-store
    __shared__ float Xs[32][128];   // [k][p]
    const int ptile = blockIdx.x;
    const int otile = blockIdx.y;
    const float* W = otile ? w_diff : w_in;
    const float* X = otile ? (const float*)g_fmax : x;
    const int pglob = ptile * 128;
    const int b = pglob >> 12;                 // /4096 (tile never crosses a b plane)
    const int hw0 = pglob & 4095;
    const float* Xbase = X + (size_t)b * 128 * HW + hw0;   // + c*HW + p
    const int t = threadIdx.x;
    const int tx = t & 15, ty = t >> 4;        // channels: ty+16*i, pixels: tx*8+j

    float acc[8][8];
    #pragma unroll
    for (int i = 0; i < 8; i++)
        #pragma unroll
        for (int j = 0; j < 8; j++) acc[i][j] = 0.f;

    #pragma unroll 1
    for (int kc = 0; kc < 128; kc += 32) {
        #pragma unroll
        for (int r = 0; r < 16; r++) {
            int idx = t + r * 256;             // 4096 weights
            int o = idx >> 5, kk = idx & 31;
            Ws[kk][o] = W[o * 128 + kc + kk];
        }
        #pragma unroll
        for (int r = 0; r < 16; r++) {
            int idx = t + r * 256;             // 4096 activations
            int kk = idx >> 7, p = idx & 127;
            Xs[kk][p] = Xbase[(size_t)(kc + kk) * HW + p];
        }
        __syncthreads();
        #pragma unroll
        for (int k = 0; k < 32; k++) {
            float a[8];
            #pragma unroll
            for (int i = 0; i < 8; i++) a[i] = Ws[k][ty + 16 * i];
            float4 b0 = *(const float4*)&Xs[k][tx * 8];
            float4 b1 = *(const float4*)&Xs[k][tx * 8 + 4];
            float bb[8] = {b0.x, b0.y, b0.z, b0.w, b1.x, b1.y, b1.z, b1.w};
            #pragma unroll
            for (int i = 0; i < 8; i++)
                #pragma unroll
                for (int j = 0; j < 8; j++) acc[i][j] = fmaf(a[i], bb[j], acc[i][j]);
        }
        __syncthreads();
    }

    // epilogue: store Y + per-channel partial sums over this tile's 128 pixels
    float s1[8], s2[8];
    #pragma unroll
    for (int i = 0; i < 8; i++) { s1[i] = 0.f; s2[i] = 0.f; }
    #pragma unroll
    for (int i = 0; i < 8; i++) {
        int c = ty + 16 * i;
        float* Yrow = g_Y + (size_t)(otile * 128 + c) * NPIX + pglob + tx * 8;
        float4 v0 = make_float4(acc[i][0], acc[i][1], acc[i][2], acc[i][3]);
        float4 v1 = make_float4(acc[i][4], acc[i][5], acc[i][6], acc[i][7]);
        *(float4*)(Yrow) = v0;
        *(float4*)(Yrow + 4) = v1;
        #pragma unroll
        for (int j = 0; j < 8; j++) { float v = acc[i][j]; s1[i] += v; s2[i] += v * v; }
    }
    #pragma unroll
    for (int off = 8; off; off >>= 1)
        #pragma unroll
        for (int i = 0; i < 8; i++) {
            s1[i] += __shfl_down_sync(0xffffffffu, s1[i], off, 16);
            s2[i] += __shfl_down_sync(0xffffffffu, s2[i], off, 16);
        }
    if (tx == 0) {
        #pragma unroll
        for (int i = 0; i < 8; i++) {
            int c = otile * 128 + ty + 16 * i;
            g_ypart[((size_t)c * 1024 + ptile) * 2 + 0] = s1[i];
            g_ypart[((size_t)c * 1024 + ptile) * 2 + 1] = s2[i];
        }
    }
}

// ---------------- reduce Y stats -> a[256], b2n[128]
__global__ void k_reduceY(const float* __restrict__ g_ibn, const float* __restrict__ be_ibn,
                          const float* __restrict__ gbn) {
    int c = blockIdx.x;      // 0..255
    int t = threadIdx.x;     // 256
    double s = 0.0, ss = 0.0;
    for (int i = t; i < 1024; i += 256) {
        s  += (double)g_ypart[((size_t)c * 1024 + i) * 2 + 0];
        ss += (double)g_ypart[((size_t)c * 1024 + i) * 2 + 1];
    }
    __shared__ double sh[256], shh[256];
    sh[t] = s; shh[t] = ss; __syncthreads();
    for (int o = 128; o; o >>= 1) {
        if (t < o) { sh[t] += sh[t + o]; shh[t] += shh[t + o]; }
        __syncthreads();
    }
    if (t == 0) {
        double mu = sh[0] / (double)NPIX;
        double var = shh[0] / (double)NPIX - mu * mu;
        float g = (c < 128) ? g_ibn[c] : gbn[c - 128];
        float a = g / sqrtf((float)var + 1e-5f);
        g_a[c] = a;
        if (c < 128) g_b2n[c] = be_ibn[c] - a * (float)mu;
    }
}

// ---------------- fold a into w_mr
__global__ void k_wfold(const float* __restrict__ w_mr) {
    int i = blockIdx.x * 256 + threadIdx.x;   // 32768
    g_Wfold[i] = w_mr[i] * g_a[i & 255];
}

// ---------------- K4: H[o][p] = sum_k Wfold[o][k] * Y[k][p]  (K=256), + partials
__global__ __launch_bounds__(256, 2) void k_convH() {
    __shared__ float Ws[32][129];
    __shared__ float Xs[32][128];
    const int ptile = blockIdx.x;
    const int pglob = ptile * 128;
    const float* Xbase = g_Y + pglob;          // [ch][NPIX] layout: + c*NPIX + p
    const int t = threadIdx.x;
    const int tx = t & 15, ty = t >> 4;

    float acc[8][8];
    #pragma unroll
    for (int i = 0; i < 8; i++)
        #pragma unroll
        for (int j = 0; j < 8; j++) acc[i][j] = 0.f;

    #pragma unroll 1
    for (int kc = 0; kc < 256; kc += 32) {
        #pragma unroll
        for (int r = 0; r < 16; r++) {
            int idx = t + r * 256;
            int o = idx >> 5, kk = idx & 31;
            Ws[kk][o] = g_Wfold[o * 256 + kc + kk];
        }
        #pragma unroll
        for (int r = 0; r < 16; r++) {
            int idx = t + r * 256;
            int kk = idx >> 7, p = idx & 127;
            Xs[kk][p] = Xbase[(size_t)(kc + kk) * NPIX + p];
        }
        __syncthreads();
        #pragma unroll
        for (int k = 0; k < 32; k++) {
            float a[8];
            #pragma unroll
            for (int i = 0; i < 8; i++) a[i] = Ws[k][ty + 16 * i];
            float4 b0 = *(const float4*)&Xs[k][tx * 8];
            float4 b1 = *(const float4*)&Xs[k][tx * 8 + 4];
            float bb[8] = {b0.x, b0.y, b0.z, b0.w, b1.x, b1.y, b1.z, b1.w};
            #pragma unroll
            for (int i = 0; i < 8; i++)
                #pragma unroll
                for (int j = 0; j < 8; j++) acc[i][j] = fmaf(a[i], bb[j], acc[i][j]);
        }
        __syncthreads();
    }

    float s1[8], s2[8];
    #pragma unroll
    for (int i = 0; i < 8; i++) { s1[i] = 0.f; s2[i] = 0.f; }
    #pragma unroll
    for (int i = 0; i < 8; i++) {
        int c = ty + 16 * i;
        float* Hrow = g_H + (size_t)c * NPIX + pglob + tx * 8;
        *(float4*)(Hrow)     = make_float4(acc[i][0], acc[i][1], acc[i][2], acc[i][3]);
        *(float4*)(Hrow + 4) = make_float4(acc[i][4], acc[i][5], acc[i][6], acc[i][7]);
        #pragma unroll
        for (int j = 0; j < 8; j++) { float v = acc[i][j]; s1[i] += v; s2[i] += v * v; }
    }
    #pragma unroll
    for (int off = 8; off; off >>= 1)
        #pragma unroll
        for (int i = 0; i < 8; i++) {
            s1[i] += __shfl_down_sync(0xffffffffu, s1[i], off, 16);
            s2[i] += __shfl_down_sync(0xffffffffu, s2[i], off, 16);
        }
    if (tx == 0) {
        #pragma unroll
        for (int i = 0; i < 8; i++) {
            int c = ty + 16 * i;
            g_hpart[((size_t)c * 1024 + ptile) * 2 + 0] = s1[i];
            g_hpart[((size_t)c * 1024 + ptile) * 2 + 1] = s2[i];
        }
    }
}

// ---------------- reduce H stats -> a3, d3
__global__ void k_reduceH(const float* __restrict__ g_mbn, const float* __restrict__ be_mbn) {
    int c = blockIdx.x;      // 0..127
    int t = threadIdx.x;
    double s = 0.0, ss = 0.0;
    for (int i = t; i < 1024; i += 256) {
        s  += (double)g_hpart[((size_t)c * 1024 + i) * 2 + 0];
        ss += (double)g_hpart[((size_t)c * 1024 + i) * 2 + 1];
    }
    __shared__ double sh[256], shh[256];
    sh[t] = s; shh[t] = ss; __syncthreads();
    for (int o = 128; o; o >>= 1) {
        if (t < o) { sh[t] += sh[t + o]; shh[t] += shh[t + o]; }
        __syncthreads();
    }
    if (t == 0) {
        double mu = sh[0] / (double)NPIX;
        double var = shh[0] / (double)NPIX - mu * mu;
        float a = g_mbn[c] / sqrtf((float)var + 1e-5f);
        g_a3[c] = a;
        g_d3[c] = be_mbn[c] - a * (float)mu;
    }
}

// ---------------- K5: out = a2*Y2 + b2n + gelu(a3*H + d3)
__global__ void k_out(float* __restrict__ out) {
    size_t i = ((size_t)blockIdx.x * 256 + threadIdx.x) * 4;   // over 16777216
    int c = (int)((i >> 12) & 127);
    size_t b = i >> 19;                         // /(128*4096)
    size_t p = b * HW + (i & 4095);             // global pixel
    float4 y = *(const float4*)(g_Y + (size_t)c * NPIX + p);
    float4 h = *(const float4*)(g_H + (size_t)c * NPIX + p);
    float a2 = g_a[c], bn = g_b2n[c], a3 = g_a3[c], d3 = g_d3[c];
    float4 o;
    o.x = fmaf(a2, y.x, bn) + gelu_exact(fmaf(a3, h.x, d3));
    o.y = fmaf(a2, y.y, bn) + gelu_exact(fmaf(a3, h.y, d3));
    o.z = fmaf(a2, y.z, bn) + gelu_exact(fmaf(a3, h.z, d3));
    o.w = fmaf(a2, y.w, bn) + gelu_exact(fmaf(a3, h.w, d3));
    *(float4*)(out + i) = o;
}

// ---------------- launch ----------------------------------------------------
extern "C" void kernel_launch(void* const* d_in, const int* in_sizes, int n_in,
                              void* d_out, int out_size) {
    const float* x      = (const float*)d_in[0];
    const float* w_diff = (const float*)d_in[1];
    // d_in[2] b_diff: cancels in BN
    const float* gbn    = (const float*)d_in[3];
    // d_in[4] be_bn: x_diff shift cancels through BN3
    const float* w_in   = (const float*)d_in[5];
    // d_in[6] b_in: cancels in BN
    const float* g_ibn  = (const float*)d_in[7];
    const float* be_ibn = (const float*)d_in[8];
    const float* w_mr   = (const float*)d_in[9];
    // d_in[10] b_mr: cancels in BN3
    const float* g_mbn  = (const float*)d_in[11];
    const float* be_mbn = (const float*)d_in[12];
    float* out = (float*)d_out;

    k_fmax<<<4096, 256>>>(x);
    k_convY<<<dim3(1024, 2), 256>>>(x, w_in, w_diff);
    k_reduceY<<<256, 256>>>(g_ibn, be_ibn, gbn);
    k_wfold<<<128, 256>>>(w_mr);
    k_convH<<<1024, 256>>>();
    k_reduceH<<<128, 256>>>(g_mbn, be_mbn);
    k_out<<<16384, 256>>>(out);
}